// round 5
// baseline (speedup 1.0000x reference)
#include <cuda_runtime.h>

#define L_SEQ 1024
#define M_DIM 128

// Final table, step-major, padded one step:
//   per step i: floats [0..127]  W[m] = dlt[m,i] * P0[m,i]   (P0 = prod_{j<i} e0[m,j])
//               floats [128..255] q[m] = dlt[m,i] / e0[m,i]
__device__ float g_tbl[(L_SEQ + 1) * 256];
// temps (step-major e0 / dlt) and per-chunk e0 products
__device__ float g_e0[L_SEQ * M_DIM];
__device__ float g_dl[L_SEQ * M_DIM];
__device__ float g_cp[8 * M_DIM];     // [c*128 + m] = prod of e0 over steps c*128..c*128+127

typedef unsigned long long u64;

__device__ __forceinline__ u64 pk2(float lo, float hi) {
    u64 r; asm("mov.b64 %0,{%1,%2};" : "=l"(r) : "f"(lo), "f"(hi)); return r;
}
__device__ __forceinline__ void upk2(u64 v, float& lo, float& hi) {
    asm("mov.b64 {%0,%1},%2;" : "=f"(lo), "=f"(hi) : "l"(v));
}
__device__ __forceinline__ u64 fma2(u64 a, u64 b, u64 c) {
    u64 r; asm("fma.rn.f32x2 %0,%1,%2,%3;" : "=l"(r) : "l"(a), "l"(b), "l"(c)); return r;
}
__device__ __forceinline__ u64 mul2(u64 a, u64 b) {
    u64 r; asm("mul.rn.f32x2 %0,%1,%2;" : "=l"(r) : "l"(a), "l"(b)); return r;
}
__device__ __forceinline__ u64 add2(u64 a, u64 b) {
    u64 r; asm("add.rn.f32x2 %0,%1,%2;" : "=l"(r) : "l"(a), "l"(b)); return r;
}
// predicated update: if (s) h_k = q_k*h_k + h_k  (4 packed FMAs under one predicate)
__device__ __forceinline__ void upd4(u64& h0, u64& h1, u64& h2, u64& h3,
                                     u64 q0, u64 q1, u64 q2, u64 q3, int s) {
    asm("{.reg .pred P; setp.ne.s32 P,%8,0;"
        "@P fma.rn.f32x2 %0,%4,%0,%0;"
        "@P fma.rn.f32x2 %1,%5,%1,%1;"
        "@P fma.rn.f32x2 %2,%6,%2,%2;"
        "@P fma.rn.f32x2 %3,%7,%3,%3;}"
        : "+l"(h0), "+l"(h1), "+l"(h2), "+l"(h3)
        : "l"(q0), "l"(q1), "l"(q2), "l"(q3), "r"(s));
}
__device__ __forceinline__ u64 shfl64_xor(unsigned mask, u64 v, int o) {
    double d = __longlong_as_double((long long)v);
    d = __shfl_xor_sync(mask, d, o);
    return (u64)__double_as_longlong(d);
}

// prepA: transpose eps [D,M,L] -> step-major e0 / dlt
__global__ void prepA(const float* __restrict__ eps) {
    int idx = blockIdx.x * blockDim.x + threadIdx.x;
    if (idx >= L_SEQ * M_DIM) return;
    int i = idx >> 7, m = idx & 127;
    float a = eps[(size_t)m * L_SEQ + i];
    float b = eps[(size_t)(M_DIM + m) * L_SEQ + i];
    g_e0[i * 128 + m] = a;
    g_dl[i * 128 + m] = b - a;
}

// prepB: per (m, chunk c of 128 steps) product of e0
__global__ void prepB() {
    int idx = blockIdx.x * blockDim.x + threadIdx.x;   // 0..1023
    int m = idx & 127, c = idx >> 7;
    float p = 1.f;
    #pragma unroll 8
    for (int t = 0; t < 128; t++)
        p *= g_e0[(c * 128 + t) * 128 + m];
    g_cp[c * 128 + m] = p;
}

// prepC: scan within chunk, write W and q
__global__ void prepC() {
    int idx = blockIdx.x * blockDim.x + threadIdx.x;   // 0..1023
    int m = idx & 127, c = idx >> 7;
    float P = 1.f;
    for (int cc = 0; cc < c; cc++) P *= g_cp[cc * 128 + m];
    for (int t = 0; t < 128; t++) {
        int i = c * 128 + t;
        float e = g_e0[i * 128 + m];
        float d = g_dl[i * 128 + m];
        g_tbl[i * 256 + m]       = d * P;
        g_tbl[i * 256 + 128 + m] = __fdividef(d, e);
        P *= e;
    }
    if (c == 0) {   // zero the pad step (prefetch target only)
        g_tbl[L_SEQ * 256 + m] = 0.f;
        g_tbl[L_SEQ * 256 + 128 + m] = 0.f;
    }
}

__global__ __launch_bounds__(128)
void arqgps_kernel(const int* __restrict__ inp, float* __restrict__ out, int nrows) {
    const unsigned FULL = 0xffffffffu;
    const int lane  = threadIdx.x & 31;
    const int r     = lane & 15;                 // lane within 16-lane slot
    const int gb    = lane & 16;                 // slot base in warp
    const int nrg   = nrows >> 1;                // row-groups of 2 rows
    const int rg_raw = blockIdx.x * (blockDim.x >> 4) + (threadIdx.x >> 4);
    const bool live = (rg_raw < nrg);
    const int rg    = live ? rg_raw : (nrg - 1);

    const ulonglong2* __restrict__ tb = reinterpret_cast<const ulonglong2*>(g_tbl);
    const int* __restrict__ i0p = inp + (size_t)(2 * rg) * L_SEQ;
    const int* __restrict__ i1p = i0p + L_SEQ;

    const u64 one2 = pk2(1.f, 1.f);
    u64 H0[4], H1[4];
    #pragma unroll
    for (int k = 0; k < 4; k++) { H0[k] = one2; H1[k] = one2; }

    const int myrow = r & 1;                                  // row this lane finalizes
    const int kksel = 2 * ((r >> 1) & 1) + ((r >> 2) & 1);    // step-in-batch finalized
    float acc = 0.f;
    int c1m = 0;                                              // 1-count for my row

    // current-step tile: W (chunks r, 16+r) and q (32+r, 48+r)
    ulonglong2 W0 = tb[r], W1 = tb[16 + r], Q0 = tb[32 + r], Q1 = tb[48 + r];

    int iv0 = __ldg(i0p + r), iv1 = __ldg(i1p + r);
    unsigned bits0 = (__ballot_sync(FULL, iv0 & 1) >> gb) & 0xffffu;
    unsigned bits1 = (__ballot_sync(FULL, iv1 & 1) >> gb) & 0xffffu;

    for (int i0 = 0; i0 < L_SEQ; i0 += 16) {
        const int ivn0 = (i0 + 16 < L_SEQ) ? __ldg(i0p + i0 + 16 + r) : 0;
        const int ivn1 = (i0 + 16 < L_SEQ) ? __ldg(i1p + i0 + 16 + r) : 0;
        const unsigned bn0 = (__ballot_sync(FULL, ivn0 & 1) >> gb) & 0xffffu;
        const unsigned bn1 = (__ballot_sync(FULL, ivn1 & 1) >> gb) & 0xffffu;
        const unsigned bitsm = myrow ? bits1 : bits0;
        const ulonglong2* __restrict__ bb = tb + (size_t)i0 * 64;

        #pragma unroll
        for (int b = 0; b < 4; b++) {
            u64 dP0[4], dP1[4];

            #pragma unroll
            for (int t = 0; t < 4; t++) {
                const int k = b * 4 + t;
                // prefetch next step's tile (valid at k=15 thanks to pad)
                ulonglong2 nW0 = bb[(k + 1) * 64 + r];
                ulonglong2 nW1 = bb[(k + 1) * 64 + 16 + r];
                ulonglong2 nQ0 = bb[(k + 1) * 64 + 32 + r];
                ulonglong2 nQ1 = bb[(k + 1) * 64 + 48 + r];

                // packed dx partials for both rows
                u64 a0 = mul2(W0.x, H0[0]), b0 = mul2(W0.y, H0[1]);
                a0 = fma2(W1.x, H0[2], a0); b0 = fma2(W1.y, H0[3], b0);
                dP0[t] = add2(a0, b0);
                u64 a1 = mul2(W0.x, H1[0]), b1 = mul2(W0.y, H1[1]);
                a1 = fma2(W1.x, H1[2], a1); b1 = fma2(W1.y, H1[3], b1);
                dP1[t] = add2(a1, b1);

                // predicated updates h *= (1 + q)
                upd4(H0[0], H0[1], H0[2], H0[3], Q0.x, Q0.y, Q1.x, Q1.y, (int)((bits0 >> k) & 1u));
                upd4(H1[0], H1[1], H1[2], H1[3], Q0.x, Q0.y, Q1.x, Q1.y, (int)((bits1 >> k) & 1u));

                W0 = nW0; W1 = nW1; Q0 = nQ0; Q1 = nQ1;
            }

            // butterfly reduce-scatter (packed): 8 values -> 1 per lane (x2 dup on bit3)
            u64 w[4];
            #pragma unroll
            for (int t = 0; t < 4; t++) {
                u64 send = (r & 1) ? dP0[t] : dP1[t];
                u64 keep = (r & 1) ? dP1[t] : dP0[t];
                w[t] = add2(keep, shfl64_xor(FULL, send, 1));
            }
            u64 u_[2];
            #pragma unroll
            for (int t = 0; t < 2; t++) {
                u64 send = (r & 2) ? w[t] : w[t + 2];
                u64 keep = (r & 2) ? w[t + 2] : w[t];
                u_[t] = add2(keep, shfl64_xor(FULL, send, 2));
            }
            u64 z64;
            {
                u64 send = (r & 4) ? u_[0] : u_[1];
                u64 keep = (r & 4) ? u_[1] : u_[0];
                z64 = add2(keep, shfl64_xor(FULL, send, 4));
            }
            float zl, zh; upk2(z64, zl, zh);
            float z = zl + zh;
            const float dxt = z + __shfl_xor_sync(FULL, z, 8);

            // finalize this lane's (row, step)
            const int kk = b * 4 + kksel;
            const int i  = i0 + kk;
            const int s  = (int)((bitsm >> kk) & 1u);
            const int c1i = c1m + __popc(bitsm & ((1u << kk) - 1u));

            const float sgn = s ? dxt : -dxt;
            const float contrib = fminf(0.f, sgn)
                                - 0.5f * __logf(1.f + __expf(-2.f * fabsf(dxt)));
            const bool dead_other = s ? ((i - c1i) >= 512) : (c1i >= 512);
            acc += dead_other ? 0.f : contrib;
        }

        c1m += __popc(bitsm);
        bits0 = bn0; bits1 = bn1;
    }

    // sum per-row partial accs within slot (keep bit0 = row separation)
    acc += __shfl_xor_sync(FULL, acc, 2);
    acc += __shfl_xor_sync(FULL, acc, 4);
    acc += __shfl_xor_sync(FULL, acc, 8);
    // each (row,step) counted twice (bit3 dup) -> 0.5x
    if (live && r == 0) out[2 * rg]     = 0.5f * acc;
    if (live && r == 1) out[2 * rg + 1] = 0.5f * acc;
}

extern "C" void kernel_launch(void* const* d_in, const int* in_sizes, int n_in,
                              void* d_out, int out_size) {
    const int*   inp = nullptr;
    const float* eps = nullptr;
    int rows = 0;
    if (in_sizes[0] == 2 * M_DIM * L_SEQ) {
        eps = (const float*)d_in[0];
        inp = (const int*)d_in[1];
        rows = in_sizes[1] / L_SEQ;
    } else {
        inp = (const int*)d_in[0];
        eps = (const float*)d_in[1];
        rows = in_sizes[0] / L_SEQ;
    }

    { int n = L_SEQ * M_DIM; prepA<<<(n + 255) / 256, 256>>>(eps); }
    prepB<<<4, 256>>>();
    prepC<<<4, 256>>>();
    {
        // 16 rows per 128-thread block (8 slots x 2 rows)
        int nrg = rows / 2;
        int rg_per_block = 128 / 16;
        int grid = (nrg + rg_per_block - 1) / rg_per_block;
        arqgps_kernel<<<grid, 128>>>(inp, (float*)d_out, rows);
    }
}

// round 6
// speedup vs baseline: 1.2524x; 1.2524x over previous
#include <cuda_runtime.h>

#define L_SEQ 1024
#define M_DIM 128

// Final table, step-major, padded two steps (prefetch depth 2):
//   per step i: floats [0..127]   W[m] = dlt[m,i] * P0[m,i]   (P0 = prod_{j<i} e0[m,j])
//               floats [128..255] q[m] = dlt[m,i] / e0[m,i]
__device__ float g_tbl[(L_SEQ + 2) * 256];
__device__ float g_e0[L_SEQ * M_DIM];
__device__ float g_dl[L_SEQ * M_DIM];
__device__ float g_cp[8 * M_DIM];

typedef unsigned long long u64;

__device__ __forceinline__ u64 pk2(float lo, float hi) {
    u64 r; asm("mov.b64 %0,{%1,%2};" : "=l"(r) : "f"(lo), "f"(hi)); return r;
}
__device__ __forceinline__ void upk2(u64 v, float& lo, float& hi) {
    asm("mov.b64 {%0,%1},%2;" : "=f"(lo), "=f"(hi) : "l"(v));
}
__device__ __forceinline__ u64 fma2(u64 a, u64 b, u64 c) {
    u64 r; asm("fma.rn.f32x2 %0,%1,%2,%3;" : "=l"(r) : "l"(a), "l"(b), "l"(c)); return r;
}
__device__ __forceinline__ u64 mul2(u64 a, u64 b) {
    u64 r; asm("mul.rn.f32x2 %0,%1,%2;" : "=l"(r) : "l"(a), "l"(b)); return r;
}
// predicated: if (s) { h0 = q0*h0 + h0; h1 = q1*h1 + h1; }
__device__ __forceinline__ void upd2(u64& h0, u64& h1, u64 q0, u64 q1, int s) {
    asm("{.reg .pred P; setp.ne.s32 P,%4,0;"
        "@P fma.rn.f32x2 %0,%2,%0,%0;"
        "@P fma.rn.f32x2 %1,%3,%1,%1;}"
        : "+l"(h0), "+l"(h1) : "l"(q0), "l"(q1), "r"(s));
}

// prepA: transpose eps [D,M,L] -> step-major e0 / dlt
__global__ void prepA(const float* __restrict__ eps) {
    int idx = blockIdx.x * blockDim.x + threadIdx.x;
    if (idx >= L_SEQ * M_DIM) return;
    int i = idx >> 7, m = idx & 127;
    float a = eps[(size_t)m * L_SEQ + i];
    float b = eps[(size_t)(M_DIM + m) * L_SEQ + i];
    g_e0[i * 128 + m] = a;
    g_dl[i * 128 + m] = b - a;
}

// prepB: per (m, chunk c of 128 steps) product of e0
__global__ void prepB() {
    int idx = blockIdx.x * blockDim.x + threadIdx.x;   // 0..1023
    int m = idx & 127, c = idx >> 7;
    float p = 1.f;
    #pragma unroll 8
    for (int t = 0; t < 128; t++)
        p *= g_e0[(c * 128 + t) * 128 + m];
    g_cp[c * 128 + m] = p;
}

// prepC: scan within chunk, write W and q; zero the 2 pad steps
__global__ void prepC() {
    int idx = blockIdx.x * blockDim.x + threadIdx.x;   // 0..1023
    int m = idx & 127, c = idx >> 7;
    float P = 1.f;
    for (int cc = 0; cc < c; cc++) P *= g_cp[cc * 128 + m];
    for (int t = 0; t < 128; t++) {
        int i = c * 128 + t;
        float e = g_e0[i * 128 + m];
        float d = g_dl[i * 128 + m];
        g_tbl[i * 256 + m]       = d * P;
        g_tbl[i * 256 + 128 + m] = __fdividef(d, e);
        P *= e;
    }
    if (c == 0) {
        g_tbl[L_SEQ * 256 + m] = 0.f;       g_tbl[L_SEQ * 256 + 128 + m] = 0.f;
        g_tbl[(L_SEQ + 1) * 256 + m] = 0.f; g_tbl[(L_SEQ + 1) * 256 + 128 + m] = 0.f;
    }
}

__global__ __launch_bounds__(128, 7)
void arqgps_kernel(const int* __restrict__ inp, float* __restrict__ out, int nrows) {
    const unsigned FULL = 0xffffffffu;
    const int lane = threadIdx.x & 31;
    const int wid  = threadIdx.x >> 5;
    const int nrg  = nrows >> 1;                     // pairs of rows; one pair per warp
    const int rg_raw = blockIdx.x * 4 + wid;
    const bool live = (rg_raw < nrg);
    const int rg = live ? rg_raw : (nrg - 1);        // clamp; never early-exit (shuffles!)

    const ulonglong2* __restrict__ tb = reinterpret_cast<const ulonglong2*>(g_tbl);
    const int* __restrict__ i0p = inp + (size_t)(2 * rg) * L_SEQ;
    const int* __restrict__ i1p = i0p + L_SEQ;

    const u64 one2 = pk2(1.f, 1.f);
    u64 H0[2] = {one2, one2}, H1[2] = {one2, one2};  // 4 m per row

    const bool b0 = lane & 1;                        // row this lane finalizes
    const bool r1 = lane & 2, r2 = lane & 4, r3 = lane & 8;
    const int tsel = ((lane >> 1) & 1) | (((lane >> 2) & 1) << 1) | (((lane >> 3) & 1) << 2);

    float acc = 0.f;
    int c1m = 0;                                     // 1-count for my row, before window

    // depth-2 tile pipeline: cur = step0, nxt = step1
    ulonglong2 Wc = tb[lane],      Qc = tb[32 + lane];
    ulonglong2 Wn = tb[64 + lane], Qn = tb[96 + lane];

    unsigned bits0 = __ballot_sync(FULL, __ldg(i0p + lane) & 1);   // 32 steps of s, row0
    unsigned bits1 = __ballot_sync(FULL, __ldg(i1p + lane) & 1);   // row1

    for (int i0 = 0; i0 < L_SEQ; i0 += 32) {
        const int nx = i0 + 32;
        const int iv0n = (nx < L_SEQ) ? __ldg(i0p + nx + lane) : 0;
        const int iv1n = (nx < L_SEQ) ? __ldg(i1p + nx + lane) : 0;
        const unsigned bn0 = __ballot_sync(FULL, iv0n & 1);
        const unsigned bn1 = __ballot_sync(FULL, iv1n & 1);
        const unsigned bitsm = b0 ? bits1 : bits0;

        #pragma unroll
        for (int b = 0; b < 4; b++) {
            float e[8];
            #pragma unroll
            for (int t = 0; t < 8; t++) {
                const int k = b * 8 + t;
                const int i = i0 + k;
                // prefetch step i+2 (pad makes this always valid)
                ulonglong2 W2 = tb[(size_t)(i + 2) * 64 + lane];
                ulonglong2 Q2 = tb[(size_t)(i + 2) * 64 + 32 + lane];

                // dx partials (4 m per row, packed)
                u64 p0 = fma2(Wc.y, H0[1], mul2(Wc.x, H0[0]));
                u64 p1 = fma2(Wc.y, H1[1], mul2(Wc.x, H1[0]));

                // h *= (1 + q) when s==1
                upd2(H0[0], H0[1], Qc.x, Qc.y, (int)((bits0 >> k) & 1u));
                upd2(H1[0], H1[1], Qc.x, Qc.y, (int)((bits1 >> k) & 1u));

                float a0, a1, a2, a3;
                upk2(p0, a0, a1); upk2(p1, a2, a3);
                const float d0 = a0 + a1, d1 = a2 + a3;
                // butterfly round 1 (row bit), fused into step loop
                const float kp = b0 ? d1 : d0;
                const float sd = b0 ? d0 : d1;
                e[t] = kp + __shfl_xor_sync(FULL, sd, 1);

                Wc = Wn; Qc = Qn; Wn = W2; Qn = Q2;
            }
            // rounds: xor2 (t bit0), xor4 (t bit1), xor8 (t bit2), xor16 (finish 32-lane sum)
            float f[4];
            #pragma unroll
            for (int u_ = 0; u_ < 4; u_++) {
                float kp = r1 ? e[2 * u_ + 1] : e[2 * u_];
                float sd = r1 ? e[2 * u_]     : e[2 * u_ + 1];
                f[u_] = kp + __shfl_xor_sync(FULL, sd, 2);
            }
            float g[2];
            #pragma unroll
            for (int v = 0; v < 2; v++) {
                float kp = r2 ? f[2 * v + 1] : f[2 * v];
                float sd = r2 ? f[2 * v]     : f[2 * v + 1];
                g[v] = kp + __shfl_xor_sync(FULL, sd, 4);
            }
            float z;
            {
                float kp = r3 ? g[1] : g[0];
                float sd = r3 ? g[0] : g[1];
                z = kp + __shfl_xor_sync(FULL, sd, 8);
            }
            const float dxt = z + __shfl_xor_sync(FULL, z, 16);

            // this lane finalizes (row = b0, step = b*8 + tsel)
            const int kk = b * 8 + tsel;
            const int i  = i0 + kk;
            const int s  = (int)((bitsm >> kk) & 1u);
            const int c1i = c1m + __popc(bitsm & ((1u << kk) - 1u));

            const float sgn = s ? dxt : -dxt;
            const float contrib = fminf(0.f, sgn)
                                - 0.5f * __logf(1.f + __expf(-2.f * fabsf(dxt)));
            const bool dead_other = s ? ((i - c1i) >= 512) : (c1i >= 512);
            acc += dead_other ? 0.f : contrib;
        }

        c1m += __popc(bitsm);
        bits0 = bn0; bits1 = bn1;
    }

    // sum acc across the 16 lanes of each row class (bit0 = row)
    acc += __shfl_xor_sync(FULL, acc, 2);
    acc += __shfl_xor_sync(FULL, acc, 4);
    acc += __shfl_xor_sync(FULL, acc, 8);
    acc += __shfl_xor_sync(FULL, acc, 16);
    // every (row, step) counted twice (lanes r and r^16) -> 0.5x
    if (live && lane < 2) out[2 * rg + lane] = 0.5f * acc;
}

extern "C" void kernel_launch(void* const* d_in, const int* in_sizes, int n_in,
                              void* d_out, int out_size) {
    const int*   inp = nullptr;
    const float* eps = nullptr;
    int rows = 0;
    if (in_sizes[0] == 2 * M_DIM * L_SEQ) {
        eps = (const float*)d_in[0];
        inp = (const int*)d_in[1];
        rows = in_sizes[1] / L_SEQ;
    } else {
        inp = (const int*)d_in[0];
        eps = (const float*)d_in[1];
        rows = in_sizes[0] / L_SEQ;
    }

    { int n = L_SEQ * M_DIM; prepA<<<(n + 255) / 256, 256>>>(eps); }
    prepB<<<4, 256>>>();
    prepC<<<4, 256>>>();
    {
        // one warp per row-pair; 4 warps (4 pairs = 8 rows) per 128-thread block
        int nrg = rows / 2;
        int grid = (nrg + 3) / 4;
        arqgps_kernel<<<grid, 128>>>(inp, (float*)d_out, rows);
    }
}

// round 7
// speedup vs baseline: 1.3647x; 1.0897x over previous
#include <cuda_runtime.h>

#define L_SEQ 1024
#define M_DIM 128

// Final table, step-major, padded two steps (prefetch depth 2):
//   per step i: floats [0..127]   W[m] = dlt[m,i] * P0[m,i]   (P0 = prod_{j<i} e0[m,j])
//               floats [128..255] q[m] = dlt[m,i] / e0[m,i]
__device__ float g_tbl[(L_SEQ + 2) * 256];
__device__ float g_e0[L_SEQ * M_DIM];
__device__ float g_dl[L_SEQ * M_DIM];
__device__ float g_cp[8 * M_DIM];

typedef unsigned long long u64;

__device__ __forceinline__ u64 pk2(float lo, float hi) {
    u64 r; asm("mov.b64 %0,{%1,%2};" : "=l"(r) : "f"(lo), "f"(hi)); return r;
}
__device__ __forceinline__ void upk2(u64 v, float& lo, float& hi) {
    asm("mov.b64 {%0,%1},%2;" : "=f"(lo), "=f"(hi) : "l"(v));
}
__device__ __forceinline__ u64 fma2(u64 a, u64 b, u64 c) {
    u64 r; asm("fma.rn.f32x2 %0,%1,%2,%3;" : "=l"(r) : "l"(a), "l"(b), "l"(c)); return r;
}
__device__ __forceinline__ u64 mul2(u64 a, u64 b) {
    u64 r; asm("mul.rn.f32x2 %0,%1,%2;" : "=l"(r) : "l"(a), "l"(b)); return r;
}
__device__ __forceinline__ u64 add2(u64 a, u64 b) {
    u64 r; asm("add.rn.f32x2 %0,%1,%2;" : "=l"(r) : "l"(a), "l"(b)); return r;
}
// predicated: if (s) { h0 = q0*h0 + h0; h1 = q1*h1 + h1; }
__device__ __forceinline__ void upd2(u64& h0, u64& h1, u64 q0, u64 q1, int s) {
    asm("{.reg .pred P; setp.ne.s32 P,%4,0;"
        "@P fma.rn.f32x2 %0,%2,%0,%0;"
        "@P fma.rn.f32x2 %1,%3,%1,%1;}"
        : "+l"(h0), "+l"(h1) : "l"(q0), "l"(q1), "r"(s));
}

// prepA: transpose eps [D,M,L] -> step-major e0 / dlt
__global__ void prepA(const float* __restrict__ eps) {
    int idx = blockIdx.x * blockDim.x + threadIdx.x;
    if (idx >= L_SEQ * M_DIM) return;
    int i = idx >> 7, m = idx & 127;
    float a = eps[(size_t)m * L_SEQ + i];
    float b = eps[(size_t)(M_DIM + m) * L_SEQ + i];
    g_e0[i * 128 + m] = a;
    g_dl[i * 128 + m] = b - a;
}

// prepB: per (m, chunk c of 128 steps) product of e0
__global__ void prepB() {
    int idx = blockIdx.x * blockDim.x + threadIdx.x;   // 0..1023
    int m = idx & 127, c = idx >> 7;
    float p = 1.f;
    #pragma unroll 8
    for (int t = 0; t < 128; t++)
        p *= g_e0[(c * 128 + t) * 128 + m];
    g_cp[c * 128 + m] = p;
}

// prepC: scan within chunk, write W and q; zero the 2 pad steps
__global__ void prepC() {
    int idx = blockIdx.x * blockDim.x + threadIdx.x;   // 0..1023
    int m = idx & 127, c = idx >> 7;
    float P = 1.f;
    for (int cc = 0; cc < c; cc++) P *= g_cp[cc * 128 + m];
    for (int t = 0; t < 128; t++) {
        int i = c * 128 + t;
        float e = g_e0[i * 128 + m];
        float d = g_dl[i * 128 + m];
        g_tbl[i * 256 + m]       = d * P;
        g_tbl[i * 256 + 128 + m] = __fdividef(d, e);
        P *= e;
    }
    if (c == 0) {
        g_tbl[L_SEQ * 256 + m] = 0.f;       g_tbl[L_SEQ * 256 + 128 + m] = 0.f;
        g_tbl[(L_SEQ + 1) * 256 + m] = 0.f; g_tbl[(L_SEQ + 1) * 256 + 128 + m] = 0.f;
    }
}

#define WIN 16                       // reduction window (steps)
#define WPAD 33                      // u64 stride per step (conflict-free phases)

__global__ __launch_bounds__(128, 7)
void arqgps_kernel(const int* __restrict__ inp, float* __restrict__ out, int nrows) {
    __shared__ u64 sp[4][WIN * WPAD];            // 4 warps x 4224 B = 16.5 KB
    const unsigned FULL = 0xffffffffu;
    const int lane = threadIdx.x & 31;
    const int wid  = threadIdx.x >> 5;
    const int nrg  = nrows >> 1;                 // one row-pair per warp
    const int rg_raw = blockIdx.x * 4 + wid;
    const bool live = (rg_raw < nrg);
    const int rg = live ? rg_raw : (nrg - 1);    // clamp; never early-exit (ballots!)

    const ulonglong2* __restrict__ tb = reinterpret_cast<const ulonglong2*>(g_tbl);
    const int* __restrict__ i0p = inp + (size_t)(2 * rg) * L_SEQ;
    const int* __restrict__ i1p = i0p + L_SEQ;

    const u64 one2 = pk2(1.f, 1.f);
    u64 H0[2] = {one2, one2}, H1[2] = {one2, one2};   // 4 m per row

    // this lane finalizes (row = wrow, window-step = wstep) each window
    const int wstep = lane & 15;
    const int wrow  = lane >> 4;

    u64* const wp = &sp[wid][lane];              // writer base: wp[t*WPAD]
    u64* const rp = &sp[wid][wstep * WPAD];      // reader base: rp[l]

    float acc = 0.f;
    int   c1m = 0;                               // 1-count for MY row before window

    // depth-2 tile pipeline
    ulonglong2 Wc = tb[lane],      Qc = tb[32 + lane];
    ulonglong2 Wn = tb[64 + lane], Qn = tb[96 + lane];

    unsigned bits0 = __ballot_sync(FULL, __ldg(i0p + lane) & 1);   // s for 32 steps, row0
    unsigned bits1 = __ballot_sync(FULL, __ldg(i1p + lane) & 1);   // row1

    for (int i0 = 0; i0 < L_SEQ; i0 += 32) {
        const int nx = i0 + 32;
        const int iv0n = (nx < L_SEQ) ? __ldg(i0p + nx + lane) : 0;
        const int iv1n = (nx < L_SEQ) ? __ldg(i1p + nx + lane) : 0;
        const unsigned bn0 = __ballot_sync(FULL, iv0n & 1);
        const unsigned bn1 = __ballot_sync(FULL, iv1n & 1);

        #pragma unroll
        for (int h = 0; h < 2; h++) {
            // ---- write phase: 16 steps, one STS.64 each, zero cross-lane deps ----
            #pragma unroll
            for (int t = 0; t < WIN; t++) {
                const int k = h * WIN + t;
                const int i = i0 + k;
                ulonglong2 W2 = tb[(size_t)(i + 2) * 64 + lane];
                ulonglong2 Q2 = tb[(size_t)(i + 2) * 64 + 32 + lane];

                u64 p0 = fma2(Wc.y, H0[1], mul2(Wc.x, H0[0]));   // row0, 4 m packed
                u64 p1 = fma2(Wc.y, H1[1], mul2(Wc.x, H1[0]));   // row1

                upd2(H0[0], H0[1], Qc.x, Qc.y, (int)((bits0 >> k) & 1u));
                upd2(H1[0], H1[1], Qc.x, Qc.y, (int)((bits1 >> k) & 1u));

                float a0, a1, a2, a3;
                upk2(p0, a0, a1); upk2(p1, a2, a3);
                wp[t * WPAD] = pk2(a0 + a1, a2 + a3);            // (row0, row1) partial

                Wc = Wn; Qc = Qn; Wn = W2; Qn = Q2;
            }
            __syncwarp();

            // ---- read phase: lane j sums 32 packed partials of step (j&15) ----
            u64 s0 = rp[0], s1 = rp[1], s2 = rp[2], s3 = rp[3];
            #pragma unroll
            for (int l = 4; l < 32; l += 4) {
                s0 = add2(s0, rp[l]);
                s1 = add2(s1, rp[l + 1]);
                s2 = add2(s2, rp[l + 2]);
                s3 = add2(s3, rp[l + 3]);
            }
            u64 st = add2(add2(s0, s1), add2(s2, s3));
            float dr0, dr1; upk2(st, dr0, dr1);
            const float dxt = wrow ? dr1 : dr0;

            // lse for (row = wrow, step = i0 + h*16 + wstep)
            const unsigned bw = ((wrow ? bits1 : bits0) >> (h * WIN)) & 0xffffu;
            const int s   = (int)((bw >> wstep) & 1u);
            const int c1i = c1m + __popc(bw & ((1u << wstep) - 1u));
            const int i   = i0 + h * WIN + wstep;

            const float sgn = s ? dxt : -dxt;
            const float contrib = fminf(0.f, sgn)
                                - 0.5f * __logf(1.f + __expf(-2.f * fabsf(dxt)));
            const bool dead_other = s ? ((i - c1i) >= 512) : (c1i >= 512);
            acc += dead_other ? 0.f : contrib;

            c1m += __popc(bw);
            __syncwarp();                        // writers of next window wait for readers
        }

        bits0 = bn0; bits1 = bn1;
    }

    // sum acc across the 16 lanes owning each row (xor < 16 stays in-group)
    acc += __shfl_xor_sync(FULL, acc, 1);
    acc += __shfl_xor_sync(FULL, acc, 2);
    acc += __shfl_xor_sync(FULL, acc, 4);
    acc += __shfl_xor_sync(FULL, acc, 8);

    if (live && (lane & 15) == 0) out[2 * rg + wrow] = acc;
}

extern "C" void kernel_launch(void* const* d_in, const int* in_sizes, int n_in,
                              void* d_out, int out_size) {
    const int*   inp = nullptr;
    const float* eps = nullptr;
    int rows = 0;
    if (in_sizes[0] == 2 * M_DIM * L_SEQ) {
        eps = (const float*)d_in[0];
        inp = (const int*)d_in[1];
        rows = in_sizes[1] / L_SEQ;
    } else {
        inp = (const int*)d_in[0];
        eps = (const float*)d_in[1];
        rows = in_sizes[0] / L_SEQ;
    }

    { int n = L_SEQ * M_DIM; prepA<<<(n + 255) / 256, 256>>>(eps); }
    prepB<<<4, 256>>>();
    prepC<<<4, 256>>>();
    {
        // one warp per row-pair; 4 warps (8 rows) per 128-thread block
        int nrg = rows / 2;
        int grid = (nrg + 3) / 4;
        arqgps_kernel<<<grid, 128>>>(inp, (float*)d_out, rows);
    }
}